// round 5
// baseline (speedup 1.0000x reference)
#include <cuda_runtime.h>
#include <math.h>

#define NTOK 32768
#define C 128

// ---------------- device scratch (no allocations allowed) ----------------
__device__ float g_z[NTOK * C];      // residual stream
__device__ float g_zn[NTOK * C];     // LN output
__device__ float g_xmid[NTOK * C];   // conv-x output (channel = h*16+dh)
__device__ float g_fxmid[NTOK * C];  // conv-fx output
__device__ float g_swt[NTOK * 256];  // slice weights [n][h][g]
__device__ float g_norm[256];        // [h][g]
__device__ float g_toknum[4096];     // [h][g][dh]
__device__ float g_ot[4096];         // [h][g][dh]

__device__ __forceinline__ float gelu_exact(float v) {
    return 0.5f * v * (1.0f + erff(v * 0.70710678118654752f));
}

__device__ __forceinline__ float warp_sum(float s) {
#pragma unroll
    for (int o = 16; o; o >>= 1) s += __shfl_xor_sync(0xffffffffu, s, o);
    return s;
}
__device__ __forceinline__ float warp_max(float s) {
#pragma unroll
    for (int o = 16; o; o >>= 1) s = fmaxf(s, __shfl_xor_sync(0xffffffffu, s, o));
    return s;
}

// ---------------- pre-MLP: z = gelu(h@W1+b1)@W2+b2+placeholder ----------------
// 32 tokens per block, 128 threads.
__global__ void __launch_bounds__(128) k_pre(
    const float* __restrict__ x, const float* __restrict__ fx,
    const float* __restrict__ W1, const float* __restrict__ b1,
    const float* __restrict__ W2, const float* __restrict__ b2,
    const float* __restrict__ ph)
{
    __shared__ float h_s[32 * 4];
    __shared__ float mid_s[32 * 256];
    int tid = threadIdx.x;
    int tok0 = blockIdx.x * 32;

    for (int i = tid; i < 128; i += 128) {
        int t = i >> 2, j = i & 3;
        h_s[i] = (j < 3) ? x[(tok0 + t) * 3 + j] : fx[tok0 + t];
    }
    __syncthreads();

#pragma unroll
    for (int rep = 0; rep < 2; rep++) {
        int m = tid + rep * 128;
        float w0 = W1[0 * 256 + m], w1 = W1[1 * 256 + m];
        float w2 = W1[2 * 256 + m], w3 = W1[3 * 256 + m];
        float bb = b1[m];
#pragma unroll
        for (int t = 0; t < 32; t++) {
            float4 hv = ((const float4*)h_s)[t];
            float v = bb + hv.x * w0 + hv.y * w1 + hv.z * w2 + hv.w * w3;
            mid_s[t * 256 + m] = gelu_exact(v);
        }
    }
    __syncthreads();

    int o = tid;
    float acc[32];
#pragma unroll
    for (int t = 0; t < 32; t++) acc[t] = 0.0f;
    for (int m4 = 0; m4 < 64; m4++) {
        int m = m4 * 4;
        float w0 = W2[(m + 0) * 128 + o], w1 = W2[(m + 1) * 128 + o];
        float w2 = W2[(m + 2) * 128 + o], w3 = W2[(m + 3) * 128 + o];
#pragma unroll
        for (int t = 0; t < 32; t++) {
            float4 v = ((const float4*)mid_s)[t * 64 + m4];
            acc[t] += v.x * w0 + v.y * w1 + v.z * w2 + v.w * w3;
        }
    }
    float bb = b2[o] + ph[o];
#pragma unroll
    for (int t = 0; t < 32; t++) g_z[(tok0 + t) * 128 + o] = acc[t] + bb;
}

// ---------------- LayerNorm: zn = LN(z)*g+b. warp per token ----------------
__global__ void __launch_bounds__(256) k_ln(
    const float* __restrict__ g, const float* __restrict__ b)
{
    int warp = threadIdx.x >> 5, lane = threadIdx.x & 31;
    int n = blockIdx.x * 8 + warp;
    float4 v = ((const float4*)g_z)[n * 32 + lane];
    float s = warp_sum(v.x + v.y + v.z + v.w);
    float mu = s * (1.0f / 128.0f);
    float q = warp_sum(v.x * v.x + v.y * v.y + v.z * v.z + v.w * v.w);
    float var = q * (1.0f / 128.0f) - mu * mu;
    float inv = rsqrtf(var + 1e-5f);
    float4 gg = ((const float4*)g)[lane];
    float4 bb = ((const float4*)b)[lane];
    float4 y;
    y.x = (v.x - mu) * inv * gg.x + bb.x;
    y.y = (v.y - mu) * inv * gg.y + bb.y;
    y.z = (v.z - mu) * inv * gg.z + bb.z;
    y.w = (v.w - mu) * inv * gg.w + bb.w;
    ((float4*)g_zn)[n * 32 + lane] = y;
}

// ---------------- conv3d 3x3x3, SAME, C=128->128 (both convs) ----------------
// grid (8,8,8): x=i-tile, y=j-tile, z in [0,8): z<4 -> convx, else convfx; oc=(z&3)*32.
// Block: 256 threads. Tile: 4x4 (i,j) x 32 k x 32 output channels.
// Thread: 8 outputs x 8 k for a fixed (i,j) line.
__global__ void __launch_bounds__(256) k_conv(
    const float* __restrict__ wx, const float* __restrict__ bx,
    const float* __restrict__ wf, const float* __restrict__ bf)
{
    const bool isfx = blockIdx.z >= 4;
    const float* __restrict__ wbase = isfx ? wf : wx;
    const float* __restrict__ bias = isfx ? bf : bx;
    float* __restrict__ out = isfx ? g_fxmid : g_xmid;
    int oc = (blockIdx.z & 3) * 32;
    int i0 = blockIdx.x * 4, j0 = blockIdx.y * 4;

    __shared__ float xs[4 * 36 * 35];   // [c][line(6x6)][k(-1..32) pitch 35]
    __shared__ float ws[32 * 4 * 27];   // [o][c][tap]

    int tid = threadIdx.x;
    int ogrp = tid >> 6;            // 0..3 (8 outputs each)
    int tg = tid & 63;
    int line = tg >> 2;             // 0..15
    int kb = (tg & 3) * 8;          // 0,8,16,24
    int li = line >> 2, lj = line & 3;

    float acc[8][8];
#pragma unroll
    for (int o = 0; o < 8; o++)
#pragma unroll
        for (int k = 0; k < 8; k++) acc[o][k] = 0.0f;

    for (int cb = 0; cb < 128; cb += 4) {
        __syncthreads();
        // load input tile: 36 lines x 34 k x 4 channels
        for (int idx = tid; idx < 1224; idx += 256) {
            int ln = idx / 34;
            int ks = idx - ln * 34;
            int ii = ln / 6, jj = ln - ii * 6;
            int gi = i0 + ii - 1, gj = j0 + jj - 1, gk = ks - 1;
            float4 v = make_float4(0.f, 0.f, 0.f, 0.f);
            if ((unsigned)gi < 32u && (unsigned)gj < 32u && (unsigned)gk < 32u) {
                v = *((const float4*)&g_zn[(((gi << 10) + (gj << 5) + gk) << 7) + cb]);
            }
            int base = ln * 35 + ks;
            xs[base + 0 * 1260] = v.x;
            xs[base + 1 * 1260] = v.y;
            xs[base + 2 * 1260] = v.z;
            xs[base + 3 * 1260] = v.w;
        }
        // load weights: 32 o x 4 c x 27 taps
        for (int idx = tid; idx < 3456; idx += 256) {
            int o = idx / 108;
            int r = idx - o * 108;
            int c = r / 27;
            int tp = r - c * 27;
            ws[idx] = wbase[((oc + o) * 128 + (cb + c)) * 27 + tp];
        }
        __syncthreads();

#pragma unroll 1
        for (int c = 0; c < 4; c++) {
#pragma unroll 1
            for (int ab = 0; ab < 9; ab++) {
                int a = ab / 3, b = ab - a * 3;
                const float* xr = &xs[c * 1260 + ((li + a) * 6 + (lj + b)) * 35 + kb];
                float xv[10];
#pragma unroll
                for (int j = 0; j < 10; j++) xv[j] = xr[j];
#pragma unroll
                for (int cc = 0; cc < 3; cc++) {
                    int tap = ab * 3 + cc;
#pragma unroll
                    for (int o = 0; o < 8; o++) {
                        float w = ws[(ogrp * 8 + o) * 108 + c * 27 + tap];
#pragma unroll
                        for (int kk = 0; kk < 8; kk++) acc[o][kk] += w * xv[kk + cc];
                    }
                }
            }
        }
    }

    int gi = i0 + li, gj = j0 + lj;
    int nbase = (gi << 10) + (gj << 5) + kb;
#pragma unroll
    for (int o = 0; o < 8; o++) {
        int och = oc + ogrp * 8 + o;
        float bv = bias[och];
#pragma unroll
        for (int kk = 0; kk < 8; kk++) out[(nbase + kk) * 128 + och] = acc[o][kk] + bv;
    }
}

// ---------------- zero slice accumulators ----------------
__global__ void k_zero() {
    int t = threadIdx.x;
    g_norm[t] = 0.0f;
    for (int i = t; i < 4096; i += 256) g_toknum[i] = 0.0f;
}

// ---------------- slice softmax + N-reductions ----------------
// 128 blocks x 256 threads; thread = (h=tid/32, g=lane); 256 tokens per block.
__global__ void __launch_bounds__(256) k_slice(
    const float* __restrict__ sw, const float* __restrict__ sb,
    const float* __restrict__ temp)
{
    __shared__ float sw_s[512];
    __shared__ float sb_s[32];
    __shared__ float xm_s[8 * 128];
    __shared__ float fx_s[8 * 128];
    int tid = threadIdx.x;
    int h = tid >> 5;
    int g = tid & 31;
    for (int i = tid; i < 512; i += 256) sw_s[i] = sw[i];
    if (tid < 32) sb_s[tid] = sb[tid];
    float invt = 1.0f / temp[h];
    float nacc = 0.0f;
    float tacc[16];
#pragma unroll
    for (int d = 0; d < 16; d++) tacc[d] = 0.0f;
    int tok0 = blockIdx.x * 256;

    for (int bt = 0; bt < 32; bt++) {
        __syncthreads();
        int tb = tok0 + bt * 8;
        for (int i = tid; i < 1024; i += 256) {
            int t = i >> 7, c = i & 127;
            xm_s[i] = g_xmid[(tb + t) * 128 + c];
            fx_s[i] = g_fxmid[(tb + t) * 128 + c];
        }
        __syncthreads();
#pragma unroll 1
        for (int t = 0; t < 8; t++) {
            float lg = sb_s[g];
#pragma unroll
            for (int d = 0; d < 16; d++) lg += xm_s[t * 128 + h * 16 + d] * sw_s[d * 32 + g];
            lg *= invt;
            float m = warp_max(lg);
            float e = expf(lg - m);
            float s = warp_sum(e);
            float w = e / s;
            g_swt[(tb + t) * 256 + tid] = w;
            nacc += w;
#pragma unroll
            for (int d = 0; d < 16; d++) tacc[d] += fx_s[t * 128 + h * 16 + d] * w;
        }
    }
    atomicAdd(&g_norm[tid], nacc);
#pragma unroll
    for (int d = 0; d < 16; d++) atomicAdd(&g_toknum[tid * 16 + d], tacc[d]);
}

// ---------------- tiny slice attention (1 block, 256 threads) ----------------
__global__ void __launch_bounds__(256) k_attn(
    const float* __restrict__ wq, const float* __restrict__ wk,
    const float* __restrict__ wv)
{
    __shared__ float k_s[4096];
    __shared__ float v_s[4096];
    int tid = threadIdx.x;
    int h = tid >> 5;
    float tokr[16];
    float nrm = g_norm[tid] + 1e-5f;
#pragma unroll
    for (int d = 0; d < 16; d++) tokr[d] = g_toknum[tid * 16 + d] / nrm;
    float q[16];
#pragma unroll
    for (int dd = 0; dd < 16; dd++) {
        float aq = 0.f, ak = 0.f, av = 0.f;
#pragma unroll
        for (int d = 0; d < 16; d++) {
            aq += tokr[d] * wq[d * 16 + dd];
            ak += tokr[d] * wk[d * 16 + dd];
            av += tokr[d] * wv[d * 16 + dd];
        }
        q[dd] = aq;
        k_s[tid * 16 + dd] = ak;
        v_s[tid * 16 + dd] = av;
    }
    __syncthreads();
    float p[32];
    float mx = -1e30f;
#pragma unroll 1
    for (int g2 = 0; g2 < 32; g2++) {
        float s = 0.f;
#pragma unroll
        for (int d = 0; d < 16; d++) s += q[d] * k_s[(h * 32 + g2) * 16 + d];
        s *= 0.25f;
        p[g2] = s;
        mx = fmaxf(mx, s);
    }
    float sum = 0.f;
#pragma unroll
    for (int g2 = 0; g2 < 32; g2++) { p[g2] = expf(p[g2] - mx); sum += p[g2]; }
    float inv = 1.0f / sum;
#pragma unroll 1
    for (int c = 0; c < 16; c++) {
        float o = 0.f;
#pragma unroll
        for (int g2 = 0; g2 < 32; g2++) o += p[g2] * v_s[(h * 32 + g2) * 16 + c];
        g_ot[tid * 16 + c] = o * inv;
    }
}

// ---------------- de-slice + wo projection + residual ----------------
// 16 tokens per block, 128 threads.
__global__ void __launch_bounds__(128) k_deslice(
    const float* __restrict__ wo, const float* __restrict__ bo)
{
    __shared__ float swt_s[16 * 256];
    __shared__ float tmp_s[16 * 128];
    int tid = threadIdx.x;
    int tok0 = blockIdx.x * 16;
    for (int i = tid; i < 4096; i += 128) swt_s[i] = g_swt[tok0 * 256 + i];
    __syncthreads();
    {
        int c = tid, h = c >> 4, cc = c & 15;
        float acc[16];
#pragma unroll
        for (int t = 0; t < 16; t++) acc[t] = 0.0f;
        for (int g = 0; g < 32; g++) {
            float ov = g_ot[(h * 32 + g) * 16 + cc];
#pragma unroll
            for (int t = 0; t < 16; t++) acc[t] += swt_s[t * 256 + h * 32 + g] * ov;
        }
#pragma unroll
        for (int t = 0; t < 16; t++) tmp_s[t * 128 + c] = acc[t];
    }
    __syncthreads();
    {
        int o = tid;
        float facc[16];
#pragma unroll
        for (int t = 0; t < 16; t++) facc[t] = 0.0f;
        for (int m4 = 0; m4 < 32; m4++) {
            int m = m4 * 4;
            float w0 = wo[(m + 0) * 128 + o], w1 = wo[(m + 1) * 128 + o];
            float w2 = wo[(m + 2) * 128 + o], w3 = wo[(m + 3) * 128 + o];
#pragma unroll
            for (int t = 0; t < 16; t++) {
                float4 v = ((const float4*)tmp_s)[t * 32 + m4];
                facc[t] += v.x * w0 + v.y * w1 + v.z * w2 + v.w * w3;
            }
        }
        float bv = bo[o];
#pragma unroll
        for (int t = 0; t < 16; t++) g_z[(tok0 + t) * 128 + o] += facc[t] + bv;
    }
}

// ---------------- MLP: z += gelu(zn@W1+b1)@W2+b2. 32 tokens/block ----------------
__global__ void __launch_bounds__(128) k_mlp(
    const float* __restrict__ W1, const float* __restrict__ b1,
    const float* __restrict__ W2, const float* __restrict__ b2)
{
    __shared__ float zn_s[32 * 128];
    __shared__ float mid_s[32 * 128];
    int tid = threadIdx.x;
    int tok0 = blockIdx.x * 32;
    for (int i = tid; i < 4096; i += 128) zn_s[i] = g_zn[tok0 * 128 + i];
    __syncthreads();
    {
        float acc[32];
#pragma unroll
        for (int t = 0; t < 32; t++) acc[t] = 0.0f;
        for (int c4 = 0; c4 < 32; c4++) {
            int c = c4 * 4;
            float w0 = W1[(c + 0) * 128 + tid], w1 = W1[(c + 1) * 128 + tid];
            float w2 = W1[(c + 2) * 128 + tid], w3 = W1[(c + 3) * 128 + tid];
#pragma unroll
            for (int t = 0; t < 32; t++) {
                float4 v = ((const float4*)zn_s)[t * 32 + c4];
                acc[t] += v.x * w0 + v.y * w1 + v.z * w2 + v.w * w3;
            }
        }
        float bb = b1[tid];
#pragma unroll
        for (int t = 0; t < 32; t++) mid_s[t * 128 + tid] = gelu_exact(acc[t] + bb);
    }
    __syncthreads();
    {
        float acc[32];
#pragma unroll
        for (int t = 0; t < 32; t++) acc[t] = 0.0f;
        for (int m4 = 0; m4 < 32; m4++) {
            int m = m4 * 4;
            float w0 = W2[(m + 0) * 128 + tid], w1 = W2[(m + 1) * 128 + tid];
            float w2 = W2[(m + 2) * 128 + tid], w3 = W2[(m + 3) * 128 + tid];
#pragma unroll
            for (int t = 0; t < 32; t++) {
                float4 v = ((const float4*)mid_s)[t * 32 + m4];
                acc[t] += v.x * w0 + v.y * w1 + v.z * w2 + v.w * w3;
            }
        }
        float bb = b2[tid];
#pragma unroll
        for (int t = 0; t < 32; t++) g_z[(tok0 + t) * 128 + tid] += acc[t] + bb;
    }
}

// ---------------- final LN + head ----------------
__global__ void __launch_bounds__(256) k_final(
    const float* __restrict__ g, const float* __restrict__ b,
    const float* __restrict__ ow, const float* __restrict__ ob,
    float* __restrict__ out)
{
    int warp = threadIdx.x >> 5, lane = threadIdx.x & 31;
    int n = blockIdx.x * 8 + warp;
    float4 v = ((const float4*)g_z)[n * 32 + lane];
    float s = warp_sum(v.x + v.y + v.z + v.w);
    float mu = s * (1.0f / 128.0f);
    float q = warp_sum(v.x * v.x + v.y * v.y + v.z * v.z + v.w * v.w);
    float var = q * (1.0f / 128.0f) - mu * mu;
    float inv = rsqrtf(var + 1e-5f);
    float4 gg = ((const float4*)g)[lane];
    float4 bb = ((const float4*)b)[lane];
    float4 w4 = ((const float4*)ow)[lane];
    float y0 = (v.x - mu) * inv * gg.x + bb.x;
    float y1 = (v.y - mu) * inv * gg.y + bb.y;
    float y2 = (v.z - mu) * inv * gg.z + bb.z;
    float y3 = (v.w - mu) * inv * gg.w + bb.w;
    float p = warp_sum(y0 * w4.x + y1 * w4.y + y2 * w4.z + y3 * w4.w);
    if (lane == 0) out[n] = p + ob[0];
}

// ---------------- host launch ----------------
extern "C" void kernel_launch(void* const* d_in, const int* in_sizes, int n_in,
                              void* d_out, int out_size)
{
    const float* x        = (const float*)d_in[0];
    const float* fx       = (const float*)d_in[1];
    const float* pre_w1   = (const float*)d_in[2];
    const float* pre_b1   = (const float*)d_in[3];
    const float* pre_w2   = (const float*)d_in[4];
    const float* pre_b2   = (const float*)d_in[5];
    const float* place    = (const float*)d_in[6];
    const float* ln1_g    = (const float*)d_in[7];
    const float* ln1_b    = (const float*)d_in[8];
    const float* convx_w  = (const float*)d_in[9];
    const float* convx_b  = (const float*)d_in[10];
    const float* convfx_w = (const float*)d_in[11];
    const float* convfx_b = (const float*)d_in[12];
    const float* slice_w  = (const float*)d_in[13];
    const float* slice_b  = (const float*)d_in[14];
    const float* temp     = (const float*)d_in[15];
    const float* wq       = (const float*)d_in[16];
    const float* wk       = (const float*)d_in[17];
    const float* wv       = (const float*)d_in[18];
    const float* wo       = (const float*)d_in[19];
    const float* bo       = (const float*)d_in[20];
    const float* ln2_g    = (const float*)d_in[21];
    const float* ln2_b    = (const float*)d_in[22];
    const float* mlp_w1   = (const float*)d_in[23];
    const float* mlp_b1   = (const float*)d_in[24];
    const float* mlp_w2   = (const float*)d_in[25];
    const float* mlp_b2   = (const float*)d_in[26];
    const float* ln3_g    = (const float*)d_in[27];
    const float* ln3_b    = (const float*)d_in[28];
    const float* out_w    = (const float*)d_in[29];
    const float* out_b    = (const float*)d_in[30];
    float* out = (float*)d_out;

    const int WCONV = 128 * 128 * 27;

    k_pre<<<NTOK / 32, 128>>>(x, fx, pre_w1, pre_b1, pre_w2, pre_b2, place);

    for (int l = 0; l < 2; l++) {
        k_ln<<<NTOK / 8, 256>>>(ln1_g + l * 128, ln1_b + l * 128);
        k_conv<<<dim3(8, 8, 8), 256>>>(convx_w + l * WCONV, convx_b + l * 128,
                                       convfx_w + l * WCONV, convfx_b + l * 128);
        k_zero<<<1, 256>>>();
        k_slice<<<128, 256>>>(slice_w + l * 512, slice_b + l * 32, temp + l * 8);
        k_attn<<<1, 256>>>(wq + l * 256, wk + l * 256, wv + l * 256);
        k_deslice<<<NTOK / 16, 128>>>(wo + l * 16384, bo + l * 128);
        k_ln<<<NTOK / 8, 256>>>(ln2_g + l * 128, ln2_b + l * 128);
        k_mlp<<<NTOK / 32, 128>>>(mlp_w1 + l * 16384, mlp_b1 + l * 128,
                                  mlp_w2 + l * 16384, mlp_b2 + l * 128);
    }
    k_final<<<NTOK / 8, 256>>>(ln3_g, ln3_b, out_w, out_b, out);
}